// round 15
// baseline (speedup 1.0000x reference)
#include <cuda_runtime.h>
#include <math.h>

// Shapes (fixed per reference)
#define BB 2
#define NN 64
#define MM 64
#define LL 30
#define EE 128
#define HH 4
#define DHH 32
#define KD 136        // 120 softmax-weight rows + 16 ew rows
#define SST 68        // S row stride (64 m, padded)
#define NBLK 128
#define NTHR 512

// ---------------- device scratch (no allocation allowed) ----------------
__device__ __align__(16) float g_WeK[4 * EE];     // We @ Wk
__device__ __align__(16) float g_ck[LL * EE];     // (be+pe[l])@Wk + bk
__device__ __align__(16) float g_b2[EE];          // bo@Wp + bp
__device__ __align__(16) float g_C[KD * EE];      // folded epilogue matrix
__device__ unsigned g_ticket = 0;                 // monotonic grid-barrier ticket

// ---------------- f32x2 packed helpers (Blackwell FFMA2) ----------------
__device__ __forceinline__ unsigned long long pk2(float a, float b) {
    unsigned long long r;
    asm("mov.b64 %0, {%1,%2};" : "=l"(r) : "f"(a), "f"(b));
    return r;
}
__device__ __forceinline__ void fma2(unsigned long long& d, unsigned long long a,
                                     unsigned long long b) {
    asm("fma.rn.f32x2 %0, %1, %2, %0;" : "+l"(d) : "l"(a), "l"(b));
}
__device__ __forceinline__ void upk2(unsigned long long v, float& a, float& b) {
    asm("mov.b64 {%0,%1}, %2;" : "=f"(a), "=f"(b) : "l"(v));
}

// ---------------- cp.async 16B (LDGSTS) ----------------------------------
__device__ __forceinline__ void cpa16(unsigned smem_addr, const void* gptr) {
    asm volatile("cp.async.cg.shared.global [%0], [%1], 16;"
                 :: "r"(smem_addr), "l"(gptr));
}
__device__ __forceinline__ unsigned smem_u32(const void* p) {
    unsigned r;
    asm("{ .reg .u64 t; cvta.to.shared.u64 t, %1; cvt.u32.u64 %0, t; }"
        : "=r"(r) : "l"(p));
    return r;
}

// ---------------- grid barrier: monotonic ticket, 1 wave, all resident ---
__device__ __forceinline__ void grid_sync() {
    __syncthreads();
    if (threadIdx.x == 0) {
        __threadfence();
        unsigned t = atomicAdd(&g_ticket, 1u);
        unsigned target = (t / NBLK + 1u) * NBLK;
        while (*(volatile unsigned*)&g_ticket < target) { __nanosleep(32); }
        __threadfence();
    }
    __syncthreads();
}

// ---------------- smem layout (floats) -----------------------------------
#define SM_C 0
#define SM_S 17408
#define SM_Q (SM_S + KD * SST)            // 26656
#define SM_AE (SM_Q + EE)                 // 26784
#define SM_R (SM_AE + EE)                 // 26912
#define SM_S0 (SM_R + 16)                 // 26928
#define SM_AX (SM_S0 + HH * LL)           // 27048
#define SM_CK (SM_AX + 8)                 // 27056 (16B aligned)
#define SM_WEK (SM_CK + LL * EE)          // 30896
#define SM_B2 (SM_WEK + 4 * EE)           // 31408
#define SM_TOTAL_FLOATS (SM_B2 + EE)      // 31536 floats = ~123.2 KB

__global__ void __launch_bounds__(NTHR, 1)
fused_kernel(const float* __restrict__ agent, const float* __restrict__ lanes,
             const float* __restrict__ We, const float* __restrict__ be,
             const float* __restrict__ Wa, const float* __restrict__ ba,
             const float* __restrict__ pe,
             const float* __restrict__ Wq, const float* __restrict__ bq,
             const float* __restrict__ Wk, const float* __restrict__ bk,
             const float* __restrict__ Wv, const float* __restrict__ bv,
             const float* __restrict__ Wo, const float* __restrict__ bo,
             const float* __restrict__ Wp, const float* __restrict__ bp,
             float* __restrict__ out) {
    extern __shared__ float sm[];
    // phase temps (live inside s_C region; dead before s_C is staged)
    float* s_tmp  = sm;            // 512
    float* s_tmp2 = sm + 512;      // 512
    float* s_a    = sm + 1024;     // 128
    float* s_v    = sm + 1152;     // 128
    float* s_D2   = sm + 1280;     // 512
    float* s_C  = sm + SM_C;
    float* s_S  = sm + SM_S;
    float* s_q  = sm + SM_Q;
    float* s_ae = sm + SM_AE;
    float* s_r  = sm + SM_R;
    float* s_s0 = sm + SM_S0;
    float* s_ax = sm + SM_AX;
    float* s_ck = sm + SM_CK;
    float* s_wek = sm + SM_WEK;
    float* s_b2 = sm + SM_B2;

    const int tid = threadIdx.x;
    const int bn = blockIdx.x;   // b*64 + n, also precompute row id
    const int b = bn >> 6;
    const int j = tid & 127, qtr = tid >> 7;   // split-k quarter
    const int warp = tid >> 5, ln = tid & 31;

    // ======== prefetch lane points at kernel top (hide L2 latency under
    // the whole pre-sync phase; depends on nothing) ========
    const bool act = (ln < LL);
    float4 pp[4];
    if (act) {
#pragma unroll
        for (int mi = 0; mi < 4; mi++)
            pp[mi] = *(const float4*)(lanes +
                        ((size_t)(b * MM + warp * 4 + mi) * LL + ln) * 4);
    }

    // ======== stage: A row (precompute blocks), ae, ax ========
    if (bn < 69 && tid >= 256 && tid < 384) {
        int i = tid - 256;
        float v;
        if (bn < 30) v = be[i] + pe[bn * EE + i];
        else if (bn < 34) v = We[(bn - 30) * EE + i];
        else if (bn < 64) v = be[i] + pe[(bn - 34) * EE + i];
        else if (bn < 68) v = We[(bn - 64) * EE + i];
        else v = bo[i];
        s_a[i] = v;
    }
    if (tid < EE) {  // ae = afeat@Wa + ba
        const float* ag = agent + bn * 16;
        float a = fmaf(ag[2], Wa[tid], ba[tid]);
#pragma unroll
        for (int i = 1; i < 12; i++) a = fmaf(ag[4 + i], Wa[i * EE + tid], a);
        s_ae[tid] = a;
    }
    if (tid == EE) {
        const float* ag = agent + bn * 16;
        float x = ag[0], y = ag[1], s = ag[3], c = ag[4];
        s_ax[0] = x; s_ax[1] = y; s_ax[2] = s; s_ax[3] = c;
        s_ax[4] = (x == 0.f && y == 0.f && s == 0.f && c == 0.f) ? 0.f : 1.f;
    }
    __syncthreads();

    // ======== stage-1 matvec partial (blocks 0..68) + q partial — split-k =
    const int k0 = qtr * 32;
    if (bn < 69) {
        const float* W = (bn < 34) ? Wv : (bn < 68) ? Wk : Wp;
        const float* wcol = W + j;
        float a0 = 0.f, a1 = 0.f, a2 = 0.f, a3 = 0.f;
#pragma unroll
        for (int k = 0; k < 32; k += 4) {
            a0 = fmaf(s_a[k0 + k],     wcol[(k0 + k) * EE],     a0);
            a1 = fmaf(s_a[k0 + k + 1], wcol[(k0 + k + 1) * EE], a1);
            a2 = fmaf(s_a[k0 + k + 2], wcol[(k0 + k + 2) * EE], a2);
            a3 = fmaf(s_a[k0 + k + 3], wcol[(k0 + k + 3) * EE], a3);
        }
        s_tmp[tid] = (a0 + a1) + (a2 + a3);
    }
    {   // q partial
        const float* wq = Wq + j;
        float a0 = 0.f, a1 = 0.f, a2 = 0.f, a3 = 0.f;
#pragma unroll
        for (int k = 0; k < 32; k += 4) {
            a0 = fmaf(s_ae[k0 + k],     wq[(k0 + k) * EE],     a0);
            a1 = fmaf(s_ae[k0 + k + 1], wq[(k0 + k + 1) * EE], a1);
            a2 = fmaf(s_ae[k0 + k + 2], wq[(k0 + k + 2) * EE], a2);
            a3 = fmaf(s_ae[k0 + k + 3], wq[(k0 + k + 3) * EE], a3);
        }
        s_tmp2[tid] = (a0 + a1) + (a2 + a3);
    }
    __syncthreads();
    if (tid < EE) {
        s_q[tid] = ((s_tmp2[tid] + s_tmp2[tid + 128]) +
                    (s_tmp2[tid + 256] + s_tmp2[tid + 384])) + bq[tid];
        if (bn < 69) {
            float acc = (s_tmp[tid] + s_tmp[tid + 128]) +
                        (s_tmp[tid + 256] + s_tmp[tid + 384]);
            if (bn < 30) s_v[tid] = acc + bv[tid];           // cv row bn
            else if (bn < 34) s_v[tid] = acc;                // WeV row bn-30
            else if (bn < 64) g_ck[(bn - 34) * EE + tid] = acc + bk[tid];
            else if (bn < 68) g_WeK[(bn - 64) * EE + tid] = acc;
            else g_b2[tid] = acc + bp[tid];
        }
    }

    // ======== blocks 0..33: finish C rows locally (D = v@Wo_h, C = D@Wp) ==
    if (bn < 34) {
        __syncthreads();
        {   // D[hh][t] = sum_d s_v[hh*32+d] * Wo[hh*32+d, t]
            const int hh = tid >> 7, t = tid & 127;
            const float* wo = Wo + (hh * DHH) * EE + t;
            const float* vp = s_v + hh * DHH;
            float a0 = 0.f, a1 = 0.f, a2 = 0.f, a3 = 0.f;
#pragma unroll
            for (int d = 0; d < DHH; d += 4) {
                a0 = fmaf(vp[d],     wo[d * EE],       a0);
                a1 = fmaf(vp[d + 1], wo[(d + 1) * EE], a1);
                a2 = fmaf(vp[d + 2], wo[(d + 2) * EE], a2);
                a3 = fmaf(vp[d + 3], wo[(d + 3) * EE], a3);
            }
            s_D2[hh * EE + t] = (a0 + a1) + (a2 + a3);
        }
        __syncthreads();
        {   // C[row][e] = sum_t D[hh][t] * Wp[t, e]
            const int hh = tid >> 7, e = tid & 127;
            const float* wp = Wp + e;
            const float* dp = s_D2 + hh * EE;
            float a0 = 0.f, a1 = 0.f, a2 = 0.f, a3 = 0.f;
#pragma unroll 8
            for (int t = 0; t < EE; t += 4) {
                a0 = fmaf(dp[t],     wp[t * EE],       a0);
                a1 = fmaf(dp[t + 1], wp[(t + 1) * EE], a1);
                a2 = fmaf(dp[t + 2], wp[(t + 2) * EE], a2);
                a3 = fmaf(dp[t + 3], wp[(t + 3) * EE], a3);
            }
            const int row = (bn < 30) ? (hh * LL + bn) : (HH * LL + hh * 4 + (bn - 30));
            g_C[row * EE + e] = (a0 + a1) + (a2 + a3);
        }
    }

    grid_sync();  // C rows, ck, WeK, b2 globally visible (single barrier)

    // ======== cp.async pipeline: group A (ck/WeK/b2), group B (C) ========
    {
        const unsigned s_ck_a = smem_u32(s_ck);
        const unsigned s_wek_a = smem_u32(s_wek);
        const unsigned s_b2_a = smem_u32(s_b2);
        const unsigned s_C_a = smem_u32(s_C);
        // group A: ck 960 f4, WeK 128 f4, b2 32 f4
        cpa16(s_ck_a + tid * 16, (const char*)g_ck + tid * 16);
        if (tid < 448)
            cpa16(s_ck_a + (512 + tid) * 16, (const char*)g_ck + (512 + tid) * 16);
        if (tid < 128) cpa16(s_wek_a + tid * 16, (const char*)g_WeK + tid * 16);
        if (tid < 32)  cpa16(s_b2_a + tid * 16, (const char*)g_b2 + tid * 16);
        asm volatile("cp.async.commit_group;" ::: "memory");
        // group B: C (4352 f4)
        const char* gsrc = (const char*)g_C;
#pragma unroll
        for (int i = 0; i < 8; i++)
            cpa16(s_C_a + (tid + i * 512) * 16, gsrc + (tid + i * 512) * 16);
        if (tid < 256)
            cpa16(s_C_a + (4096 + tid) * 16, gsrc + (4096 + tid) * 16);
        asm volatile("cp.async.commit_group;" ::: "memory");
    }
    asm volatile("cp.async.wait_group 1;" ::: "memory");  // group A done
    __syncthreads();

    // ======== r / s0 (from smem) ========
    const float invs = 0.17677669529663687f;  // 1/sqrt(32)
    if (tid < 16) {
        int h = tid >> 2, c = tid & 3;
        const float* wk = s_wek + c * EE + h * DHH;
        const float* qp = s_q + h * DHH;
        float a0 = 0.f, a1 = 0.f, a2 = 0.f, a3 = 0.f;
#pragma unroll
        for (int d = 0; d < DHH; d += 4) {
            a0 = fmaf(wk[d], qp[d], a0);
            a1 = fmaf(wk[d + 1], qp[d + 1], a1);
            a2 = fmaf(wk[d + 2], qp[d + 2], a2);
            a3 = fmaf(wk[d + 3], qp[d + 3], a3);
        }
        s_r[tid] = ((a0 + a1) + (a2 + a3)) * invs;
    } else if (tid < 16 + HH * LL) {
        int t = tid - 16;
        int h = t / LL, l = t % LL;
        const float* qp = s_q + h * DHH;
        const float* cp = s_ck + l * EE + h * DHH;
        float a0 = 0.f, a1 = 0.f, a2 = 0.f, a3 = 0.f;
#pragma unroll
        for (int d = 0; d < DHH; d += 4) {
            a0 = fmaf(qp[d], cp[d], a0);
            a1 = fmaf(qp[d + 1], cp[d + 1], a1);
            a2 = fmaf(qp[d + 2], cp[d + 2], a2);
            a3 = fmaf(qp[d + 3], cp[d + 3], a3);
        }
        s_s0[t] = ((a0 + a1) + (a2 + a3)) * invs;
    }
    __syncthreads();

    // ======== phase B: 16 warps x 4 m each ========
    const float axv = s_ax[0], ayv = s_ax[1], as1 = s_ax[2], ac1 = s_ax[3], f1 = s_ax[4];
    float rr[16];
#pragma unroll
    for (int i = 0; i < 16; i++) rr[i] = s_r[i];

#pragma unroll 1
    for (int mi = 0; mi < 4; mi++) {
        const int m = warp * 4 + mi;
        float ex = 0.f, ey = 0.f, es = 0.f, ec = 0.f;
        float e[4];
        if (act) {
            const float4 p = pp[mi];
            float f2 = (p.x == 0.f && p.y == 0.f && p.z == 0.f && p.w == 0.f) ? 0.f : 1.f;
            float f = f1 * f2;
            float dx = p.x - axv, dy = p.y - ayv;
            ex = (ac1 * dx + as1 * dy) * 0.1f * f;
            ey = (ac1 * dy - as1 * dx) * 0.1f * f;
            es = (p.z * ac1 - p.w * as1) * f;
            ec = (p.w * ac1 + p.z * as1) * f;
            // scores are O(1): linear layers are 1/sqrt(din)-scaled, so
            // softmax without max-subtraction is exact in fp32 here.
#pragma unroll
            for (int h = 0; h < 4; h++)
                e[h] = __expf(ex * rr[h * 4] + ey * rr[h * 4 + 1] +
                              es * rr[h * 4 + 2] + ec * rr[h * 4 + 3] +
                              s_s0[h * LL + ln]);
        } else {
#pragma unroll
            for (int h = 0; h < 4; h++) e[h] = 0.f;
        }
        // merged 4-sum butterfly: 6 shuffles down, rcp, 3 shuffles back
        float ka, kb, kc;
        {
            float sa = (ln & 16) ? e[0] : e[2];
            ka = ((ln & 16) ? e[2] : e[0]) + __shfl_xor_sync(0xffffffffu, sa, 16);
            float sb = (ln & 16) ? e[1] : e[3];
            kb = ((ln & 16) ? e[3] : e[1]) + __shfl_xor_sync(0xffffffffu, sb, 16);
            float sc2 = (ln & 8) ? ka : kb;
            kc = ((ln & 8) ? kb : ka) + __shfl_xor_sync(0xffffffffu, sc2, 8);
            kc += __shfl_xor_sync(0xffffffffu, kc, 4);
            kc += __shfl_xor_sync(0xffffffffu, kc, 2);
            kc += __shfl_xor_sync(0xffffffffu, kc, 1);
        }
        // kc = sum for head h_lane = 2*bit4(ln) + bit3(ln)
        float rin = __frcp_rn(kc);
        float r4[4];
        {
            float other8 = __shfl_xor_sync(0xffffffffu, rin, 8);
            float rA = (ln & 8) ? other8 : rin;   // h = 2*bit4 + 0
            float rB = (ln & 8) ? rin : other8;   // h = 2*bit4 + 1
            float oA = __shfl_xor_sync(0xffffffffu, rA, 16);
            float oB = __shfl_xor_sync(0xffffffffu, rB, 16);
            r4[0] = (ln & 16) ? oA : rA;
            r4[1] = (ln & 16) ? oB : rB;
            r4[2] = (ln & 16) ? rA : oA;
            r4[3] = (ln & 16) ? rB : oB;
        }
        float wgt[4];
#pragma unroll
        for (int h = 0; h < 4; h++) wgt[h] = e[h] * r4[h];
        if (act) {
#pragma unroll
            for (int h = 0; h < 4; h++) s_S[(h * LL + ln) * SST + m] = wgt[h];
        }
        // ew reduction: 16 values over 32 lanes, merged butterfly
        float p16[16];
#pragma unroll
        for (int h = 0; h < 4; h++) {
            p16[h * 4 + 0] = wgt[h] * ex;
            p16[h * 4 + 1] = wgt[h] * ey;
            p16[h * 4 + 2] = wgt[h] * es;
            p16[h * 4 + 3] = wgt[h] * ec;
        }
        float v8[8];
#pragma unroll
        for (int i = 0; i < 8; i++) {
            float keep = (ln & 16) ? p16[i + 8] : p16[i];
            float send = (ln & 16) ? p16[i] : p16[i + 8];
            v8[i] = keep + __shfl_xor_sync(0xffffffffu, send, 16);
        }
        float v4[4];
#pragma unroll
        for (int i = 0; i < 4; i++) {
            float keep = (ln & 8) ? v8[i + 4] : v8[i];
            float send = (ln & 8) ? v8[i] : v8[i + 4];
            v4[i] = keep + __shfl_xor_sync(0xffffffffu, send, 8);
        }
        float v2[2];
#pragma unroll
        for (int i = 0; i < 2; i++) {
            float keep = (ln & 4) ? v4[i + 2] : v4[i];
            float send = (ln & 4) ? v4[i] : v4[i + 2];
            v2[i] = keep + __shfl_xor_sync(0xffffffffu, send, 4);
        }
        float v1;
        {
            float keep = (ln & 2) ? v2[1] : v2[0];
            float send = (ln & 2) ? v2[0] : v2[1];
            v1 = keep + __shfl_xor_sync(0xffffffffu, send, 2);
            v1 += __shfl_xor_sync(0xffffffffu, v1, 1);
        }
        if (!(ln & 1)) {
            int idx = ((ln >> 4) & 1) * 8 + ((ln >> 3) & 1) * 4 +
                      ((ln >> 2) & 1) * 2 + ((ln >> 1) & 1);
            s_S[(HH * LL + idx) * SST + m] = v1;
        }
    }

    // wait for prefetched C, then GEMM
    asm volatile("cp.async.wait_group 0;" ::: "memory");
    __syncthreads();

    // ======== GEMM: OUT[64,128] = S^T[64,136] @ C[136,128] + b2 ========
    // k-split: warps 0-7 k in [0,68), warps 8-15 k in [68,136).
    // warp (w&7) owns m = (w&7)*8..+7 ; lane te owns e = te*4..+3
    const int te = ln;
    const int w8 = (warp & 7) * 8;
    const bool gA = warp < 8;
    const int kbeg = gA ? 0 : 68;
    unsigned long long acc[4][4];
    if (gA) {
        const float4 bvv = *(const float4*)&s_b2[te * 4];
#pragma unroll
        for (int mp = 0; mp < 4; mp++) {
            acc[mp][0] = pk2(bvv.x, bvv.x);
            acc[mp][1] = pk2(bvv.y, bvv.y);
            acc[mp][2] = pk2(bvv.z, bvv.z);
            acc[mp][3] = pk2(bvv.w, bvv.w);
        }
    } else {
#pragma unroll
        for (int mp = 0; mp < 4; mp++)
#pragma unroll
            for (int i = 0; i < 4; i++) acc[mp][i] = pk2(0.f, 0.f);
    }
#pragma unroll 17
    for (int k = kbeg; k < kbeg + 68; k++) {
        const float4 c4 = *(const float4*)&s_C[k * EE + te * 4];
        const float4 sA = *(const float4*)&s_S[k * SST + w8];
        const float4 sB = *(const float4*)&s_S[k * SST + w8 + 4];
        unsigned long long cc0 = pk2(c4.x, c4.x), cc1 = pk2(c4.y, c4.y);
        unsigned long long cc2 = pk2(c4.z, c4.z), cc3 = pk2(c4.w, c4.w);
        unsigned long long sp[4] = {pk2(sA.x, sA.y), pk2(sA.z, sA.w),
                                    pk2(sB.x, sB.y), pk2(sB.z, sB.w)};
#pragma unroll
        for (int mp = 0; mp < 4; mp++) {
            fma2(acc[mp][0], sp[mp], cc0);
            fma2(acc[mp][1], sp[mp], cc1);
            fma2(acc[mp][2], sp[mp], cc2);
            fma2(acc[mp][3], sp[mp], cc3);
        }
    }
    __syncthreads();  // all s_C reads done; s_C reusable as reduction scratch
    float* s_red = s_C;  // [m*EE + e], 8192 floats
    if (!gA) {
#pragma unroll
        for (int mp = 0; mp < 4; mp++) {
            float lo0, hi0, lo1, hi1, lo2, hi2, lo3, hi3;
            upk2(acc[mp][0], lo0, hi0);
            upk2(acc[mp][1], lo1, hi1);
            upk2(acc[mp][2], lo2, hi2);
            upk2(acc[mp][3], lo3, hi3);
            int m0 = w8 + mp * 2;
            *(float4*)&s_red[m0 * EE + te * 4] = make_float4(lo0, lo1, lo2, lo3);
            *(float4*)&s_red[(m0 + 1) * EE + te * 4] = make_float4(hi0, hi1, hi2, hi3);
        }
    }
    __syncthreads();
    if (gA) {
        float* outb = out + (size_t)bn * MM * EE;
#pragma unroll
        for (int mp = 0; mp < 4; mp++) {
            float lo0, hi0, lo1, hi1, lo2, hi2, lo3, hi3;
            upk2(acc[mp][0], lo0, hi0);
            upk2(acc[mp][1], lo1, hi1);
            upk2(acc[mp][2], lo2, hi2);
            upk2(acc[mp][3], lo3, hi3);
            int m0 = w8 + mp * 2;
            const float4 ra = *(const float4*)&s_red[m0 * EE + te * 4];
            const float4 rb = *(const float4*)&s_red[(m0 + 1) * EE + te * 4];
            *(float4*)&outb[(size_t)m0 * EE + te * 4] =
                make_float4(lo0 + ra.x, lo1 + ra.y, lo2 + ra.z, lo3 + ra.w);
            *(float4*)&outb[(size_t)(m0 + 1) * EE + te * 4] =
                make_float4(hi0 + rb.x, hi1 + rb.y, hi2 + rb.z, hi3 + rb.w);
        }
    }
}

// =========================== launch ======================================
extern "C" void kernel_launch(void* const* d_in, const int* in_sizes, int n_in,
                              void* d_out, int out_size) {
    const float* agent = (const float*)d_in[0];
    const float* lanes = (const float*)d_in[1];
    const float* We = (const float*)d_in[2];
    const float* be = (const float*)d_in[3];
    const float* Wa = (const float*)d_in[4];
    const float* ba = (const float*)d_in[5];
    const float* pe = (const float*)d_in[6];
    const float* Wq = (const float*)d_in[7];
    const float* bq = (const float*)d_in[8];
    const float* Wk = (const float*)d_in[9];
    const float* bk = (const float*)d_in[10];
    const float* Wv = (const float*)d_in[11];
    const float* bv = (const float*)d_in[12];
    const float* Wo = (const float*)d_in[13];
    const float* bo = (const float*)d_in[14];
    const float* Wp = (const float*)d_in[15];
    const float* bp = (const float*)d_in[16];
    float* outp = (float*)d_out;

    const int smem_bytes = SM_TOTAL_FLOATS * sizeof(float);  // ~123.2 KB
    cudaFuncSetAttribute(fused_kernel, cudaFuncAttributeMaxDynamicSharedMemorySize,
                         smem_bytes);

    fused_kernel<<<NBLK, NTHR, smem_bytes>>>(agent, lanes, We, be, Wa, ba, pe,
                                             Wq, bq, Wk, bk, Wv, bv, Wo, bo, Wp, bp,
                                             outp);
}

// round 16
// speedup vs baseline: 1.0622x; 1.0622x over previous
#include <cuda_runtime.h>
#include <math.h>

// Shapes (fixed per reference)
#define BB 2
#define NN 64
#define MM 64
#define LL 30
#define EE 128
#define HH 4
#define DHH 32
#define KD 136        // 120 softmax-weight rows + 16 ew rows
#define SST 68        // S row stride (64 m, padded)
#define NBLK 128
#define NTHR 512

// ---------------- device scratch (no allocation allowed) ----------------
__device__ __align__(16) float g_WeK[4 * EE];     // We @ Wk
__device__ __align__(16) float g_ck[LL * EE];     // (be+pe[l])@Wk + bk
__device__ __align__(16) float g_b2[EE];          // bo@Wp + bp
__device__ __align__(16) float g_C[KD * EE];      // folded epilogue matrix
__device__ unsigned g_ticket = 0;                 // monotonic grid-barrier ticket

// ---------------- f32x2 packed helpers (Blackwell FFMA2) ----------------
__device__ __forceinline__ unsigned long long pk2(float a, float b) {
    unsigned long long r;
    asm("mov.b64 %0, {%1,%2};" : "=l"(r) : "f"(a), "f"(b));
    return r;
}
__device__ __forceinline__ void fma2(unsigned long long& d, unsigned long long a,
                                     unsigned long long b) {
    asm("fma.rn.f32x2 %0, %1, %2, %0;" : "+l"(d) : "l"(a), "l"(b));
}
__device__ __forceinline__ void upk2(unsigned long long v, float& a, float& b) {
    asm("mov.b64 {%0,%1}, %2;" : "=f"(a), "=f"(b) : "l"(v));
}

// ---------------- cp.async 16B (LDGSTS) ----------------------------------
__device__ __forceinline__ void cpa16(unsigned smem_addr, const void* gptr) {
    asm volatile("cp.async.cg.shared.global [%0], [%1], 16;"
                 :: "r"(smem_addr), "l"(gptr));
}
__device__ __forceinline__ unsigned smem_u32(const void* p) {
    unsigned r;
    asm("{ .reg .u64 t; cvta.to.shared.u64 t, %1; cvt.u32.u64 %0, t; }"
        : "=r"(r) : "l"(p));
    return r;
}

// ---------------- grid barrier: monotonic ticket, 1 wave, all resident ---
__device__ __forceinline__ void grid_sync() {
    __syncthreads();
    if (threadIdx.x == 0) {
        __threadfence();
        unsigned t = atomicAdd(&g_ticket, 1u);
        unsigned target = (t / NBLK + 1u) * NBLK;
        while (*(volatile unsigned*)&g_ticket < target) { __nanosleep(32); }
        __threadfence();
    }
    __syncthreads();
}

// ---------------- smem layout (floats) -----------------------------------
#define SM_C 0
#define SM_S 17408
#define SM_Q (SM_S + KD * SST)            // 26656
#define SM_AE (SM_Q + EE)                 // 26784
#define SM_R (SM_AE + EE)                 // 26912
#define SM_S0 (SM_R + 16)                 // 26928
#define SM_AX (SM_S0 + HH * LL)           // 27048
#define SM_CK (SM_AX + 8)                 // 27056 (16B aligned)
#define SM_WEK (SM_CK + LL * EE)          // 30896
#define SM_B2 (SM_WEK + 4 * EE)           // 31408
#define SM_TOTAL_FLOATS (SM_B2 + EE)      // 31536 floats = ~123.2 KB
// pre-barrier-only scratch: Wp staged at sm[1792 .. 1792+16384) — overlaps
// the tail of s_C and head of s_S, both dead until after Wp is consumed.
#define SM_WP 1792

__global__ void __launch_bounds__(NTHR, 1)
fused_kernel(const float* __restrict__ agent, const float* __restrict__ lanes,
             const float* __restrict__ We, const float* __restrict__ be,
             const float* __restrict__ Wa, const float* __restrict__ ba,
             const float* __restrict__ pe,
             const float* __restrict__ Wq, const float* __restrict__ bq,
             const float* __restrict__ Wk, const float* __restrict__ bk,
             const float* __restrict__ Wv, const float* __restrict__ bv,
             const float* __restrict__ Wo, const float* __restrict__ bo,
             const float* __restrict__ Wp, const float* __restrict__ bp,
             float* __restrict__ out) {
    extern __shared__ float sm[];
    // phase temps (live inside s_C region; dead before s_C is staged)
    float* s_tmp  = sm;            // 512
    float* s_tmp2 = sm + 512;      // 512
    float* s_a    = sm + 1024;     // 128
    float* s_v    = sm + 1152;     // 128
    float* s_D2   = sm + 1280;     // 512
    float* s_wp   = sm + SM_WP;    // 16384 (pre-barrier only, blocks 0..33)
    float* s_C  = sm + SM_C;
    float* s_S  = sm + SM_S;
    float* s_q  = sm + SM_Q;
    float* s_ae = sm + SM_AE;
    float* s_r  = sm + SM_R;
    float* s_s0 = sm + SM_S0;
    float* s_ax = sm + SM_AX;
    float* s_ck = sm + SM_CK;
    float* s_wek = sm + SM_WEK;
    float* s_b2 = sm + SM_B2;

    const int tid = threadIdx.x;
    const int bn = blockIdx.x;   // b*64 + n, also precompute row id
    const int b = bn >> 6;
    const int j = tid & 127, qtr = tid >> 7;   // split-k quarter

    // ======== blocks 0..33: prefetch Wp into smem for the C stage ========
    if (bn < 34) {
        const unsigned wp_a = smem_u32(s_wp);
        const char* g = (const char*)Wp;
#pragma unroll
        for (int i = 0; i < 8; i++)
            cpa16(wp_a + (tid + i * 512) * 16, g + (tid + i * 512) * 16);
        asm volatile("cp.async.commit_group;" ::: "memory");
    }

    // ======== stage: A row (precompute blocks), ae, ax ========
    if (bn < 69 && tid >= 256 && tid < 384) {
        int i = tid - 256;
        float v;
        if (bn < 30) v = be[i] + pe[bn * EE + i];
        else if (bn < 34) v = We[(bn - 30) * EE + i];
        else if (bn < 64) v = be[i] + pe[(bn - 34) * EE + i];
        else if (bn < 68) v = We[(bn - 64) * EE + i];
        else v = bo[i];
        s_a[i] = v;
    }
    if (tid < EE) {  // ae = afeat@Wa + ba
        const float* ag = agent + bn * 16;
        float a = fmaf(ag[2], Wa[tid], ba[tid]);
#pragma unroll
        for (int i = 1; i < 12; i++) a = fmaf(ag[4 + i], Wa[i * EE + tid], a);
        s_ae[tid] = a;
    }
    if (tid == EE) {
        const float* ag = agent + bn * 16;
        float x = ag[0], y = ag[1], s = ag[3], c = ag[4];
        s_ax[0] = x; s_ax[1] = y; s_ax[2] = s; s_ax[3] = c;
        s_ax[4] = (x == 0.f && y == 0.f && s == 0.f && c == 0.f) ? 0.f : 1.f;
    }
    __syncthreads();

    // ======== stage-1 matvec partial (blocks 0..68) + q partial — split-k =
    const int k0 = qtr * 32;
    if (bn < 69) {
        const float* W = (bn < 34) ? Wv : (bn < 68) ? Wk : Wp;
        const float* wcol = W + j;
        float a0 = 0.f, a1 = 0.f, a2 = 0.f, a3 = 0.f;
#pragma unroll
        for (int k = 0; k < 32; k += 4) {
            a0 = fmaf(s_a[k0 + k],     wcol[(k0 + k) * EE],     a0);
            a1 = fmaf(s_a[k0 + k + 1], wcol[(k0 + k + 1) * EE], a1);
            a2 = fmaf(s_a[k0 + k + 2], wcol[(k0 + k + 2) * EE], a2);
            a3 = fmaf(s_a[k0 + k + 3], wcol[(k0 + k + 3) * EE], a3);
        }
        s_tmp[tid] = (a0 + a1) + (a2 + a3);
    }
    {   // q partial
        const float* wq = Wq + j;
        float a0 = 0.f, a1 = 0.f, a2 = 0.f, a3 = 0.f;
#pragma unroll
        for (int k = 0; k < 32; k += 4) {
            a0 = fmaf(s_ae[k0 + k],     wq[(k0 + k) * EE],     a0);
            a1 = fmaf(s_ae[k0 + k + 1], wq[(k0 + k + 1) * EE], a1);
            a2 = fmaf(s_ae[k0 + k + 2], wq[(k0 + k + 2) * EE], a2);
            a3 = fmaf(s_ae[k0 + k + 3], wq[(k0 + k + 3) * EE], a3);
        }
        s_tmp2[tid] = (a0 + a1) + (a2 + a3);
    }
    __syncthreads();
    if (tid < EE) {
        s_q[tid] = ((s_tmp2[tid] + s_tmp2[tid + 128]) +
                    (s_tmp2[tid + 256] + s_tmp2[tid + 384])) + bq[tid];
        if (bn < 69) {
            float acc = (s_tmp[tid] + s_tmp[tid + 128]) +
                        (s_tmp[tid + 256] + s_tmp[tid + 384]);
            if (bn < 30) s_v[tid] = acc + bv[tid];           // cv row bn
            else if (bn < 34) s_v[tid] = acc;                // WeV row bn-30
            else if (bn < 64) g_ck[(bn - 34) * EE + tid] = acc + bk[tid];
            else if (bn < 68) g_WeK[(bn - 64) * EE + tid] = acc;
            else g_b2[tid] = acc + bp[tid];
        }
    }

    // ======== blocks 0..33: finish C rows locally (D = v@Wo_h, C = D@Wp) ==
    if (bn < 34) {
        __syncthreads();
        {   // D[hh][t] = sum_d s_v[hh*32+d] * Wo[hh*32+d, t]
            const int hh = tid >> 7, t = tid & 127;
            const float* wo = Wo + (hh * DHH) * EE + t;
            const float* vp = s_v + hh * DHH;
            float a0 = 0.f, a1 = 0.f, a2 = 0.f, a3 = 0.f;
#pragma unroll
            for (int d = 0; d < DHH; d += 4) {
                a0 = fmaf(vp[d],     wo[d * EE],       a0);
                a1 = fmaf(vp[d + 1], wo[(d + 1) * EE], a1);
                a2 = fmaf(vp[d + 2], wo[(d + 2) * EE], a2);
                a3 = fmaf(vp[d + 3], wo[(d + 3) * EE], a3);
            }
            s_D2[hh * EE + t] = (a0 + a1) + (a2 + a3);
        }
        // wait for staged Wp before reading it from smem
        asm volatile("cp.async.wait_group 0;" ::: "memory");
        __syncthreads();
        {   // C[row][e] = sum_t D[hh][t] * Wp[t, e]  (Wp from smem)
            const int hh = tid >> 7, e = tid & 127;
            const float* wp = s_wp + e;
            const float* dp = s_D2 + hh * EE;
            float a0 = 0.f, a1 = 0.f, a2 = 0.f, a3 = 0.f;
#pragma unroll 8
            for (int t = 0; t < EE; t += 4) {
                a0 = fmaf(dp[t],     wp[t * EE],       a0);
                a1 = fmaf(dp[t + 1], wp[(t + 1) * EE], a1);
                a2 = fmaf(dp[t + 2], wp[(t + 2) * EE], a2);
                a3 = fmaf(dp[t + 3], wp[(t + 3) * EE], a3);
            }
            const int row = (bn < 30) ? (hh * LL + bn) : (HH * LL + hh * 4 + (bn - 30));
            g_C[row * EE + e] = (a0 + a1) + (a2 + a3);
        }
    }

    grid_sync();  // C rows, ck, WeK, b2 globally visible (single barrier)

    // ======== cp.async pipeline: group A (ck/WeK/b2), group B (C) ========
    {
        const unsigned s_ck_a = smem_u32(s_ck);
        const unsigned s_wek_a = smem_u32(s_wek);
        const unsigned s_b2_a = smem_u32(s_b2);
        const unsigned s_C_a = smem_u32(s_C);
        // group A: ck 960 f4, WeK 128 f4, b2 32 f4
        cpa16(s_ck_a + tid * 16, (const char*)g_ck + tid * 16);
        if (tid < 448)
            cpa16(s_ck_a + (512 + tid) * 16, (const char*)g_ck + (512 + tid) * 16);
        if (tid < 128) cpa16(s_wek_a + tid * 16, (const char*)g_WeK + tid * 16);
        if (tid < 32)  cpa16(s_b2_a + tid * 16, (const char*)g_b2 + tid * 16);
        asm volatile("cp.async.commit_group;" ::: "memory");
        // group B: C (4352 f4)
        const char* gsrc = (const char*)g_C;
#pragma unroll
        for (int i = 0; i < 8; i++)
            cpa16(s_C_a + (tid + i * 512) * 16, gsrc + (tid + i * 512) * 16);
        if (tid < 256)
            cpa16(s_C_a + (4096 + tid) * 16, gsrc + (4096 + tid) * 16);
        asm volatile("cp.async.commit_group;" ::: "memory");
    }
    asm volatile("cp.async.wait_group 1;" ::: "memory");  // group A done
    __syncthreads();

    // ======== r / s0 (from smem) ========
    const float invs = 0.17677669529663687f;  // 1/sqrt(32)
    if (tid < 16) {
        int h = tid >> 2, c = tid & 3;
        const float* wk = s_wek + c * EE + h * DHH;
        const float* qp = s_q + h * DHH;
        float a0 = 0.f, a1 = 0.f, a2 = 0.f, a3 = 0.f;
#pragma unroll
        for (int d = 0; d < DHH; d += 4) {
            a0 = fmaf(wk[d], qp[d], a0);
            a1 = fmaf(wk[d + 1], qp[d + 1], a1);
            a2 = fmaf(wk[d + 2], qp[d + 2], a2);
            a3 = fmaf(wk[d + 3], qp[d + 3], a3);
        }
        s_r[tid] = ((a0 + a1) + (a2 + a3)) * invs;
    } else if (tid < 16 + HH * LL) {
        int t = tid - 16;
        int h = t / LL, l = t % LL;
        const float* qp = s_q + h * DHH;
        const float* cp = s_ck + l * EE + h * DHH;
        float a0 = 0.f, a1 = 0.f, a2 = 0.f, a3 = 0.f;
#pragma unroll
        for (int d = 0; d < DHH; d += 4) {
            a0 = fmaf(qp[d], cp[d], a0);
            a1 = fmaf(qp[d + 1], cp[d + 1], a1);
            a2 = fmaf(qp[d + 2], cp[d + 2], a2);
            a3 = fmaf(qp[d + 3], cp[d + 3], a3);
        }
        s_s0[t] = ((a0 + a1) + (a2 + a3)) * invs;
    }
    __syncthreads();

    // ======== phase B: 16 warps x 4 m each ========
    const int warp = tid >> 5, ln = tid & 31;
    const float axv = s_ax[0], ayv = s_ax[1], as1 = s_ax[2], ac1 = s_ax[3], f1 = s_ax[4];
    float rr[16];
#pragma unroll
    for (int i = 0; i < 16; i++) rr[i] = s_r[i];

    const bool act = (ln < LL);
    float4 pp[4];
    if (act) {
#pragma unroll
        for (int mi = 0; mi < 4; mi++)
            pp[mi] = *(const float4*)(lanes +
                        ((size_t)(b * MM + warp * 4 + mi) * LL + ln) * 4);
    }

#pragma unroll 1
    for (int mi = 0; mi < 4; mi++) {
        const int m = warp * 4 + mi;
        float ex = 0.f, ey = 0.f, es = 0.f, ec = 0.f;
        float e[4];
        if (act) {
            const float4 p = pp[mi];
            float f2 = (p.x == 0.f && p.y == 0.f && p.z == 0.f && p.w == 0.f) ? 0.f : 1.f;
            float f = f1 * f2;
            float dx = p.x - axv, dy = p.y - ayv;
            ex = (ac1 * dx + as1 * dy) * 0.1f * f;
            ey = (ac1 * dy - as1 * dx) * 0.1f * f;
            es = (p.z * ac1 - p.w * as1) * f;
            ec = (p.w * ac1 + p.z * as1) * f;
            // scores are O(1): linear layers are 1/sqrt(din)-scaled, so
            // softmax without max-subtraction is exact in fp32 here.
#pragma unroll
            for (int h = 0; h < 4; h++)
                e[h] = __expf(ex * rr[h * 4] + ey * rr[h * 4 + 1] +
                              es * rr[h * 4 + 2] + ec * rr[h * 4 + 3] +
                              s_s0[h * LL + ln]);
        } else {
#pragma unroll
            for (int h = 0; h < 4; h++) e[h] = 0.f;
        }
        // merged 4-sum butterfly: 6 shuffles down, rcp, 3 shuffles back
        float ka, kb, kc;
        {
            float sa = (ln & 16) ? e[0] : e[2];
            ka = ((ln & 16) ? e[2] : e[0]) + __shfl_xor_sync(0xffffffffu, sa, 16);
            float sb = (ln & 16) ? e[1] : e[3];
            kb = ((ln & 16) ? e[3] : e[1]) + __shfl_xor_sync(0xffffffffu, sb, 16);
            float sc2 = (ln & 8) ? ka : kb;
            kc = ((ln & 8) ? kb : ka) + __shfl_xor_sync(0xffffffffu, sc2, 8);
            kc += __shfl_xor_sync(0xffffffffu, kc, 4);
            kc += __shfl_xor_sync(0xffffffffu, kc, 2);
            kc += __shfl_xor_sync(0xffffffffu, kc, 1);
        }
        // kc = sum for head h_lane = 2*bit4(ln) + bit3(ln)
        float rin = __frcp_rn(kc);
        float r4[4];
        {
            float other8 = __shfl_xor_sync(0xffffffffu, rin, 8);
            float rA = (ln & 8) ? other8 : rin;   // h = 2*bit4 + 0
            float rB = (ln & 8) ? rin : other8;   // h = 2*bit4 + 1
            float oA = __shfl_xor_sync(0xffffffffu, rA, 16);
            float oB = __shfl_xor_sync(0xffffffffu, rB, 16);
            r4[0] = (ln & 16) ? oA : rA;
            r4[1] = (ln & 16) ? oB : rB;
            r4[2] = (ln & 16) ? rA : oA;
            r4[3] = (ln & 16) ? rB : oB;
        }
        float wgt[4];
#pragma unroll
        for (int h = 0; h < 4; h++) wgt[h] = e[h] * r4[h];
        if (act) {
#pragma unroll
            for (int h = 0; h < 4; h++) s_S[(h * LL + ln) * SST + m] = wgt[h];
        }
        // ew reduction: 16 values over 32 lanes, merged butterfly
        float p16[16];
#pragma unroll
        for (int h = 0; h < 4; h++) {
            p16[h * 4 + 0] = wgt[h] * ex;
            p16[h * 4 + 1] = wgt[h] * ey;
            p16[h * 4 + 2] = wgt[h] * es;
            p16[h * 4 + 3] = wgt[h] * ec;
        }
        float v8[8];
#pragma unroll
        for (int i = 0; i < 8; i++) {
            float keep = (ln & 16) ? p16[i + 8] : p16[i];
            float send = (ln & 16) ? p16[i] : p16[i + 8];
            v8[i] = keep + __shfl_xor_sync(0xffffffffu, send, 16);
        }
        float v4[4];
#pragma unroll
        for (int i = 0; i < 4; i++) {
            float keep = (ln & 8) ? v8[i + 4] : v8[i];
            float send = (ln & 8) ? v8[i] : v8[i + 4];
            v4[i] = keep + __shfl_xor_sync(0xffffffffu, send, 8);
        }
        float v2[2];
#pragma unroll
        for (int i = 0; i < 2; i++) {
            float keep = (ln & 4) ? v4[i + 2] : v4[i];
            float send = (ln & 4) ? v4[i] : v4[i + 2];
            v2[i] = keep + __shfl_xor_sync(0xffffffffu, send, 4);
        }
        float v1;
        {
            float keep = (ln & 2) ? v2[1] : v2[0];
            float send = (ln & 2) ? v2[0] : v2[1];
            v1 = keep + __shfl_xor_sync(0xffffffffu, send, 2);
            v1 += __shfl_xor_sync(0xffffffffu, v1, 1);
        }
        if (!(ln & 1)) {
            int idx = ((ln >> 4) & 1) * 8 + ((ln >> 3) & 1) * 4 +
                      ((ln >> 2) & 1) * 2 + ((ln >> 1) & 1);
            s_S[(HH * LL + idx) * SST + m] = v1;
        }
    }

    // wait for prefetched C, then GEMM
    asm volatile("cp.async.wait_group 0;" ::: "memory");
    __syncthreads();

    // ======== GEMM: OUT[64,128] = S^T[64,136] @ C[136,128] + b2 ========
    // k-split: warps 0-7 k in [0,68), warps 8-15 k in [68,136).
    // warp (w&7) owns m = (w&7)*8..+7 ; lane te owns e = te*4..+3
    const int te = ln;
    const int w8 = (warp & 7) * 8;
    const bool gA = warp < 8;
    const int kbeg = gA ? 0 : 68;
    unsigned long long acc[4][4];
    if (gA) {
        const float4 bvv = *(const float4*)&s_b2[te * 4];
#pragma unroll
        for (int mp = 0; mp < 4; mp++) {
            acc[mp][0] = pk2(bvv.x, bvv.x);
            acc[mp][1] = pk2(bvv.y, bvv.y);
            acc[mp][2] = pk2(bvv.z, bvv.z);
            acc[mp][3] = pk2(bvv.w, bvv.w);
        }
    } else {
#pragma unroll
        for (int mp = 0; mp < 4; mp++)
#pragma unroll
            for (int i = 0; i < 4; i++) acc[mp][i] = pk2(0.f, 0.f);
    }
#pragma unroll 4
    for (int k = kbeg; k < kbeg + 68; k++) {
        const float4 c4 = *(const float4*)&s_C[k * EE + te * 4];
        const float4 sA = *(const float4*)&s_S[k * SST + w8];
        const float4 sB = *(const float4*)&s_S[k * SST + w8 + 4];
        unsigned long long cc0 = pk2(c4.x, c4.x), cc1 = pk2(c4.y, c4.y);
        unsigned long long cc2 = pk2(c4.z, c4.z), cc3 = pk2(c4.w, c4.w);
        unsigned long long sp[4] = {pk2(sA.x, sA.y), pk2(sA.z, sA.w),
                                    pk2(sB.x, sB.y), pk2(sB.z, sB.w)};
#pragma unroll
        for (int mp = 0; mp < 4; mp++) {
            fma2(acc[mp][0], sp[mp], cc0);
            fma2(acc[mp][1], sp[mp], cc1);
            fma2(acc[mp][2], sp[mp], cc2);
            fma2(acc[mp][3], sp[mp], cc3);
        }
    }
    __syncthreads();  // all s_C reads done; s_C reusable as reduction scratch
    float* s_red = s_C;  // [m*EE + e], 8192 floats
    if (!gA) {
#pragma unroll
        for (int mp = 0; mp < 4; mp++) {
            float lo0, hi0, lo1, hi1, lo2, hi2, lo3, hi3;
            upk2(acc[mp][0], lo0, hi0);
            upk2(acc[mp][1], lo1, hi1);
            upk2(acc[mp][2], lo2, hi2);
            upk2(acc[mp][3], lo3, hi3);
            int m0 = w8 + mp * 2;
            *(float4*)&s_red[m0 * EE + te * 4] = make_float4(lo0, lo1, lo2, lo3);
            *(float4*)&s_red[(m0 + 1) * EE + te * 4] = make_float4(hi0, hi1, hi2, hi3);
        }
    }
    __syncthreads();
    if (gA) {
        float* outb = out + (size_t)bn * MM * EE;
#pragma unroll
        for (int mp = 0; mp < 4; mp++) {
            float lo0, hi0, lo1, hi1, lo2, hi2, lo3, hi3;
            upk2(acc[mp][0], lo0, hi0);
            upk2(acc[mp][1], lo1, hi1);
            upk2(acc[mp][2], lo2, hi2);
            upk2(acc[mp][3], lo3, hi3);
            int m0 = w8 + mp * 2;
            const float4 ra = *(const float4*)&s_red[m0 * EE + te * 4];
            const float4 rb = *(const float4*)&s_red[(m0 + 1) * EE + te * 4];
            *(float4*)&outb[(size_t)m0 * EE + te * 4] =
                make_float4(lo0 + ra.x, lo1 + ra.y, lo2 + ra.z, lo3 + ra.w);
            *(float4*)&outb[(size_t)(m0 + 1) * EE + te * 4] =
                make_float4(hi0 + rb.x, hi1 + rb.y, hi2 + rb.z, hi3 + rb.w);
        }
    }
}

// =========================== launch ======================================
extern "C" void kernel_launch(void* const* d_in, const int* in_sizes, int n_in,
                              void* d_out, int out_size) {
    const float* agent = (const float*)d_in[0];
    const float* lanes = (const float*)d_in[1];
    const float* We = (const float*)d_in[2];
    const float* be = (const float*)d_in[3];
    const float* Wa = (const float*)d_in[4];
    const float* ba = (const float*)d_in[5];
    const float* pe = (const float*)d_in[6];
    const float* Wq = (const float*)d_in[7];
    const float* bq = (const float*)d_in[8];
    const float* Wk = (const float*)d_in[9];
    const float* bk = (const float*)d_in[10];
    const float* Wv = (const float*)d_in[11];
    const float* bv = (const float*)d_in[12];
    const float* Wo = (const float*)d_in[13];
    const float* bo = (const float*)d_in[14];
    const float* Wp = (const float*)d_in[15];
    const float* bp = (const float*)d_in[16];
    float* outp = (float*)d_out;

    const int smem_bytes = SM_TOTAL_FLOATS * sizeof(float);  // ~123.2 KB
    cudaFuncSetAttribute(fused_kernel, cudaFuncAttributeMaxDynamicSharedMemorySize,
                         smem_bytes);

    fused_kernel<<<NBLK, NTHR, smem_bytes>>>(agent, lanes, We, be, Wa, ba, pe,
                                             Wq, bq, Wk, bk, Wv, bv, Wo, bo, Wp, bp,
                                             outp);
}

// round 17
// speedup vs baseline: 1.0878x; 1.0241x over previous
#include <cuda_runtime.h>
#include <math.h>

// Shapes (fixed per reference)
#define BB 2
#define NN 64
#define MM 64
#define LL 30
#define EE 128
#define HH 4
#define DHH 32
#define KD 136        // 120 softmax-weight rows + 16 ew rows
#define SST 68        // S row stride (64 m, padded)
#define NBLK 128
#define NTHR 512

// ---------------- device scratch (no allocation allowed) ----------------
__device__ __align__(16) float g_WeK[4 * EE];     // We @ Wk
__device__ __align__(16) float g_ck[LL * EE];     // (be+pe[l])@Wk + bk
__device__ __align__(16) float g_b2[EE];          // bo@Wp + bp
__device__ __align__(16) float g_C[KD * EE];      // folded epilogue matrix
__device__ unsigned g_ticket = 0;                 // monotonic grid-barrier ticket

// ---------------- f32x2 packed helpers (Blackwell FFMA2) ----------------
__device__ __forceinline__ unsigned long long pk2(float a, float b) {
    unsigned long long r;
    asm("mov.b64 %0, {%1,%2};" : "=l"(r) : "f"(a), "f"(b));
    return r;
}
__device__ __forceinline__ void fma2(unsigned long long& d, unsigned long long a,
                                     unsigned long long b) {
    asm("fma.rn.f32x2 %0, %1, %2, %0;" : "+l"(d) : "l"(a), "l"(b));
}
__device__ __forceinline__ void upk2(unsigned long long v, float& a, float& b) {
    asm("mov.b64 {%0,%1}, %2;" : "=f"(a), "=f"(b) : "l"(v));
}

// ---------------- cp.async 16B (LDGSTS) ----------------------------------
__device__ __forceinline__ void cpa16(unsigned smem_addr, const void* gptr) {
    asm volatile("cp.async.cg.shared.global [%0], [%1], 16;"
                 :: "r"(smem_addr), "l"(gptr));
}
__device__ __forceinline__ unsigned smem_u32(const void* p) {
    unsigned r;
    asm("{ .reg .u64 t; cvta.to.shared.u64 t, %1; cvt.u32.u64 %0, t; }"
        : "=r"(r) : "l"(p));
    return r;
}

// ---------------- grid barrier: monotonic ticket, 1 wave, all resident ---
__device__ __forceinline__ void grid_sync() {
    __syncthreads();
    if (threadIdx.x == 0) {
        __threadfence();
        unsigned t = atomicAdd(&g_ticket, 1u);
        unsigned target = (t / NBLK + 1u) * NBLK;
        while (*(volatile unsigned*)&g_ticket < target) { __nanosleep(32); }
        __threadfence();
    }
    __syncthreads();
}

// ---------------- smem layout (floats) -----------------------------------
#define SM_C 0
#define SM_S 17408
#define SM_Q (SM_S + KD * SST)            // 26656
#define SM_AE (SM_Q + EE)                 // 26784
#define SM_R (SM_AE + EE)                 // 26912
#define SM_S0 (SM_R + 16)                 // 26928
#define SM_AX (SM_S0 + HH * LL)           // 27048
#define SM_CK (SM_AX + 8)                 // 27056 (16B aligned)
#define SM_WEK (SM_CK + LL * EE)          // 30896
#define SM_B2 (SM_WEK + 4 * EE)           // 31408
#define SM_TOTAL_FLOATS (SM_B2 + EE)      // 31536 floats = ~123.2 KB
// pre-barrier-only scratch: Wp staged at sm[1792 .. 1792+16384) — overlaps
// the tail of s_C and head of s_S, both dead until after Wp is consumed.
#define SM_WP 1792

__global__ void __launch_bounds__(NTHR, 1)
fused_kernel(const float* __restrict__ agent, const float* __restrict__ lanes,
             const float* __restrict__ We, const float* __restrict__ be,
             const float* __restrict__ Wa, const float* __restrict__ ba,
             const float* __restrict__ pe,
             const float* __restrict__ Wq, const float* __restrict__ bq,
             const float* __restrict__ Wk, const float* __restrict__ bk,
             const float* __restrict__ Wv, const float* __restrict__ bv,
             const float* __restrict__ Wo, const float* __restrict__ bo,
             const float* __restrict__ Wp, const float* __restrict__ bp,
             float* __restrict__ out) {
    extern __shared__ float sm[];
    // phase temps (live inside s_C region; dead before s_C is staged)
    float* s_tmp  = sm;            // 512
    float* s_tmp2 = sm + 512;      // 512
    float* s_a    = sm + 1024;     // 128
    float* s_v    = sm + 1152;     // 128
    float* s_D2   = sm + 1280;     // 512
    float* s_wp   = sm + SM_WP;    // 16384 (pre-barrier only, blocks 0..33)
    float* s_C  = sm + SM_C;
    float* s_S  = sm + SM_S;
    float* s_q  = sm + SM_Q;
    float* s_ae = sm + SM_AE;
    float* s_r  = sm + SM_R;
    float* s_s0 = sm + SM_S0;
    float* s_ax = sm + SM_AX;
    float* s_ck = sm + SM_CK;
    float* s_wek = sm + SM_WEK;
    float* s_b2 = sm + SM_B2;

    const int tid = threadIdx.x;
    const int bn = blockIdx.x;   // b*64 + n, also precompute row id
    const int b = bn >> 6;
    const int j = tid & 127, qtr = tid >> 7;   // split-k quarter

    // ======== blocks 0..33: prefetch Wp into smem for the C stage ========
    if (bn < 34) {
        const unsigned wp_a = smem_u32(s_wp);
        const char* g = (const char*)Wp;
#pragma unroll
        for (int i = 0; i < 8; i++)
            cpa16(wp_a + (tid + i * 512) * 16, g + (tid + i * 512) * 16);
        asm volatile("cp.async.commit_group;" ::: "memory");
    }

    // ======== stage: A row (precompute blocks), ae, ax ========
    if (bn < 69 && tid >= 256 && tid < 384) {
        int i = tid - 256;
        float v;
        if (bn < 30) v = be[i] + pe[bn * EE + i];
        else if (bn < 34) v = We[(bn - 30) * EE + i];
        else if (bn < 64) v = be[i] + pe[(bn - 34) * EE + i];
        else if (bn < 68) v = We[(bn - 64) * EE + i];
        else v = bo[i];
        s_a[i] = v;
    }
    if (tid < EE) {  // ae = afeat@Wa + ba
        const float* ag = agent + bn * 16;
        float a = fmaf(ag[2], Wa[tid], ba[tid]);
#pragma unroll
        for (int i = 1; i < 12; i++) a = fmaf(ag[4 + i], Wa[i * EE + tid], a);
        s_ae[tid] = a;
    }
    if (tid == EE) {
        const float* ag = agent + bn * 16;
        float x = ag[0], y = ag[1], s = ag[3], c = ag[4];
        s_ax[0] = x; s_ax[1] = y; s_ax[2] = s; s_ax[3] = c;
        s_ax[4] = (x == 0.f && y == 0.f && s == 0.f && c == 0.f) ? 0.f : 1.f;
    }
    __syncthreads();

    // ======== stage-1 matvec partial (blocks 0..68) + q partial — split-k =
    const int k0 = qtr * 32;
    if (bn < 69) {
        const float* W = (bn < 34) ? Wv : (bn < 68) ? Wk : Wp;
        const float* wcol = W + j;
        float a0 = 0.f, a1 = 0.f, a2 = 0.f, a3 = 0.f;
#pragma unroll
        for (int k = 0; k < 32; k += 4) {
            a0 = fmaf(s_a[k0 + k],     wcol[(k0 + k) * EE],     a0);
            a1 = fmaf(s_a[k0 + k + 1], wcol[(k0 + k + 1) * EE], a1);
            a2 = fmaf(s_a[k0 + k + 2], wcol[(k0 + k + 2) * EE], a2);
            a3 = fmaf(s_a[k0 + k + 3], wcol[(k0 + k + 3) * EE], a3);
        }
        s_tmp[tid] = (a0 + a1) + (a2 + a3);
    }
    {   // q partial
        const float* wq = Wq + j;
        float a0 = 0.f, a1 = 0.f, a2 = 0.f, a3 = 0.f;
#pragma unroll
        for (int k = 0; k < 32; k += 4) {
            a0 = fmaf(s_ae[k0 + k],     wq[(k0 + k) * EE],     a0);
            a1 = fmaf(s_ae[k0 + k + 1], wq[(k0 + k + 1) * EE], a1);
            a2 = fmaf(s_ae[k0 + k + 2], wq[(k0 + k + 2) * EE], a2);
            a3 = fmaf(s_ae[k0 + k + 3], wq[(k0 + k + 3) * EE], a3);
        }
        s_tmp2[tid] = (a0 + a1) + (a2 + a3);
    }
    __syncthreads();
    if (tid < EE) {
        s_q[tid] = ((s_tmp2[tid] + s_tmp2[tid + 128]) +
                    (s_tmp2[tid + 256] + s_tmp2[tid + 384])) + bq[tid];
        if (bn < 69) {
            float acc = (s_tmp[tid] + s_tmp[tid + 128]) +
                        (s_tmp[tid + 256] + s_tmp[tid + 384]);
            if (bn < 30) s_v[tid] = acc + bv[tid];           // cv row bn
            else if (bn < 34) s_v[tid] = acc;                // WeV row bn-30
            else if (bn < 64) g_ck[(bn - 34) * EE + tid] = acc + bk[tid];
            else if (bn < 68) g_WeK[(bn - 64) * EE + tid] = acc;
            else g_b2[tid] = acc + bp[tid];
        }
    }

    // ======== blocks 0..33: finish C rows locally (D = v@Wo_h, C = D@Wp) ==
    if (bn < 34) {
        __syncthreads();
        {   // D[hh][t] = sum_d s_v[hh*32+d] * Wo[hh*32+d, t]
            const int hh = tid >> 7, t = tid & 127;
            const float* wo = Wo + (hh * DHH) * EE + t;
            const float* vp = s_v + hh * DHH;
            float a0 = 0.f, a1 = 0.f, a2 = 0.f, a3 = 0.f;
#pragma unroll
            for (int d = 0; d < DHH; d += 4) {
                a0 = fmaf(vp[d],     wo[d * EE],       a0);
                a1 = fmaf(vp[d + 1], wo[(d + 1) * EE], a1);
                a2 = fmaf(vp[d + 2], wo[(d + 2) * EE], a2);
                a3 = fmaf(vp[d + 3], wo[(d + 3) * EE], a3);
            }
            s_D2[hh * EE + t] = (a0 + a1) + (a2 + a3);
        }
        // wait for staged Wp before reading it from smem
        asm volatile("cp.async.wait_group 0;" ::: "memory");
        __syncthreads();
        {   // C[row][e] = sum_t D[hh][t] * Wp[t, e]  (Wp from smem)
            const int hh = tid >> 7, e = tid & 127;
            const float* wp = s_wp + e;
            const float* dp = s_D2 + hh * EE;
            float a0 = 0.f, a1 = 0.f, a2 = 0.f, a3 = 0.f;
#pragma unroll 8
            for (int t = 0; t < EE; t += 4) {
                a0 = fmaf(dp[t],     wp[t * EE],       a0);
                a1 = fmaf(dp[t + 1], wp[(t + 1) * EE], a1);
                a2 = fmaf(dp[t + 2], wp[(t + 2) * EE], a2);
                a3 = fmaf(dp[t + 3], wp[(t + 3) * EE], a3);
            }
            const int row = (bn < 30) ? (hh * LL + bn) : (HH * LL + hh * 4 + (bn - 30));
            g_C[row * EE + e] = (a0 + a1) + (a2 + a3);
        }
    }

    grid_sync();  // C rows, ck, WeK, b2 globally visible (single barrier)

    // ======== cp.async pipeline: group A (ck/WeK/b2), group B (C) ========
    {
        const unsigned s_ck_a = smem_u32(s_ck);
        const unsigned s_wek_a = smem_u32(s_wek);
        const unsigned s_b2_a = smem_u32(s_b2);
        const unsigned s_C_a = smem_u32(s_C);
        // group A: ck 960 f4, WeK 128 f4, b2 32 f4
        cpa16(s_ck_a + tid * 16, (const char*)g_ck + tid * 16);
        if (tid < 448)
            cpa16(s_ck_a + (512 + tid) * 16, (const char*)g_ck + (512 + tid) * 16);
        if (tid < 128) cpa16(s_wek_a + tid * 16, (const char*)g_WeK + tid * 16);
        if (tid < 32)  cpa16(s_b2_a + tid * 16, (const char*)g_b2 + tid * 16);
        asm volatile("cp.async.commit_group;" ::: "memory");
        // group B: C (4352 f4)
        const char* gsrc = (const char*)g_C;
#pragma unroll
        for (int i = 0; i < 8; i++)
            cpa16(s_C_a + (tid + i * 512) * 16, gsrc + (tid + i * 512) * 16);
        if (tid < 256)
            cpa16(s_C_a + (4096 + tid) * 16, gsrc + (4096 + tid) * 16);
        asm volatile("cp.async.commit_group;" ::: "memory");
    }
    asm volatile("cp.async.wait_group 1;" ::: "memory");  // group A done
    __syncthreads();

    // ======== r / s0 (from smem) ========
    const float invs = 0.17677669529663687f;  // 1/sqrt(32)
    if (tid < 16) {
        int h = tid >> 2, c = tid & 3;
        const float* wk = s_wek + c * EE + h * DHH;
        const float* qp = s_q + h * DHH;
        float a0 = 0.f, a1 = 0.f, a2 = 0.f, a3 = 0.f;
#pragma unroll
        for (int d = 0; d < DHH; d += 4) {
            a0 = fmaf(wk[d], qp[d], a0);
            a1 = fmaf(wk[d + 1], qp[d + 1], a1);
            a2 = fmaf(wk[d + 2], qp[d + 2], a2);
            a3 = fmaf(wk[d + 3], qp[d + 3], a3);
        }
        s_r[tid] = ((a0 + a1) + (a2 + a3)) * invs;
    } else if (tid < 16 + HH * LL) {
        int t = tid - 16;
        int h = t / LL, l = t % LL;
        const float* qp = s_q + h * DHH;
        const float* cp = s_ck + l * EE + h * DHH;
        float a0 = 0.f, a1 = 0.f, a2 = 0.f, a3 = 0.f;
#pragma unroll
        for (int d = 0; d < DHH; d += 4) {
            a0 = fmaf(qp[d], cp[d], a0);
            a1 = fmaf(qp[d + 1], cp[d + 1], a1);
            a2 = fmaf(qp[d + 2], cp[d + 2], a2);
            a3 = fmaf(qp[d + 3], cp[d + 3], a3);
        }
        s_s0[t] = ((a0 + a1) + (a2 + a3)) * invs;
    }
    __syncthreads();

    // ======== phase B: 16 warps x 4 m each (mi unrolled 2x for ILP) ======
    const int warp = tid >> 5, ln = tid & 31;
    const float axv = s_ax[0], ayv = s_ax[1], as1 = s_ax[2], ac1 = s_ax[3], f1 = s_ax[4];
    float rr[16];
#pragma unroll
    for (int i = 0; i < 16; i++) rr[i] = s_r[i];

    const bool act = (ln < LL);
    float4 pp[4];
    if (act) {
#pragma unroll
        for (int mi = 0; mi < 4; mi++)
            pp[mi] = *(const float4*)(lanes +
                        ((size_t)(b * MM + warp * 4 + mi) * LL + ln) * 4);
    }

#pragma unroll 2
    for (int mi = 0; mi < 4; mi++) {
        const int m = warp * 4 + mi;
        float ex = 0.f, ey = 0.f, es = 0.f, ec = 0.f;
        float e[4];
        if (act) {
            const float4 p = pp[mi];
            float f2 = (p.x == 0.f && p.y == 0.f && p.z == 0.f && p.w == 0.f) ? 0.f : 1.f;
            float f = f1 * f2;
            float dx = p.x - axv, dy = p.y - ayv;
            ex = (ac1 * dx + as1 * dy) * 0.1f * f;
            ey = (ac1 * dy - as1 * dx) * 0.1f * f;
            es = (p.z * ac1 - p.w * as1) * f;
            ec = (p.w * ac1 + p.z * as1) * f;
            // scores are O(1): linear layers are 1/sqrt(din)-scaled, so
            // softmax without max-subtraction is exact in fp32 here.
#pragma unroll
            for (int h = 0; h < 4; h++)
                e[h] = __expf(ex * rr[h * 4] + ey * rr[h * 4 + 1] +
                              es * rr[h * 4 + 2] + ec * rr[h * 4 + 3] +
                              s_s0[h * LL + ln]);
        } else {
#pragma unroll
            for (int h = 0; h < 4; h++) e[h] = 0.f;
        }
        // merged 4-sum butterfly: 6 shuffles down, rcp, 3 shuffles back
        float ka, kb, kc;
        {
            float sa = (ln & 16) ? e[0] : e[2];
            ka = ((ln & 16) ? e[2] : e[0]) + __shfl_xor_sync(0xffffffffu, sa, 16);
            float sb = (ln & 16) ? e[1] : e[3];
            kb = ((ln & 16) ? e[3] : e[1]) + __shfl_xor_sync(0xffffffffu, sb, 16);
            float sc2 = (ln & 8) ? ka : kb;
            kc = ((ln & 8) ? kb : ka) + __shfl_xor_sync(0xffffffffu, sc2, 8);
            kc += __shfl_xor_sync(0xffffffffu, kc, 4);
            kc += __shfl_xor_sync(0xffffffffu, kc, 2);
            kc += __shfl_xor_sync(0xffffffffu, kc, 1);
        }
        // kc = sum for head h_lane = 2*bit4(ln) + bit3(ln)
        float rin = __frcp_rn(kc);
        float r4[4];
        {
            float other8 = __shfl_xor_sync(0xffffffffu, rin, 8);
            float rA = (ln & 8) ? other8 : rin;   // h = 2*bit4 + 0
            float rB = (ln & 8) ? rin : other8;   // h = 2*bit4 + 1
            float oA = __shfl_xor_sync(0xffffffffu, rA, 16);
            float oB = __shfl_xor_sync(0xffffffffu, rB, 16);
            r4[0] = (ln & 16) ? oA : rA;
            r4[1] = (ln & 16) ? oB : rB;
            r4[2] = (ln & 16) ? rA : oA;
            r4[3] = (ln & 16) ? rB : oB;
        }
        float wgt[4];
#pragma unroll
        for (int h = 0; h < 4; h++) wgt[h] = e[h] * r4[h];
        if (act) {
#pragma unroll
            for (int h = 0; h < 4; h++) s_S[(h * LL + ln) * SST + m] = wgt[h];
        }
        // ew reduction: 16 values over 32 lanes, merged butterfly
        float p16[16];
#pragma unroll
        for (int h = 0; h < 4; h++) {
            p16[h * 4 + 0] = wgt[h] * ex;
            p16[h * 4 + 1] = wgt[h] * ey;
            p16[h * 4 + 2] = wgt[h] * es;
            p16[h * 4 + 3] = wgt[h] * ec;
        }
        float v8[8];
#pragma unroll
        for (int i = 0; i < 8; i++) {
            float keep = (ln & 16) ? p16[i + 8] : p16[i];
            float send = (ln & 16) ? p16[i] : p16[i + 8];
            v8[i] = keep + __shfl_xor_sync(0xffffffffu, send, 16);
        }
        float v4[4];
#pragma unroll
        for (int i = 0; i < 4; i++) {
            float keep = (ln & 8) ? v8[i + 4] : v8[i];
            float send = (ln & 8) ? v8[i] : v8[i + 4];
            v4[i] = keep + __shfl_xor_sync(0xffffffffu, send, 8);
        }
        float v2[2];
#pragma unroll
        for (int i = 0; i < 2; i++) {
            float keep = (ln & 4) ? v4[i + 2] : v4[i];
            float send = (ln & 4) ? v4[i] : v4[i + 2];
            v2[i] = keep + __shfl_xor_sync(0xffffffffu, send, 4);
        }
        float v1;
        {
            float keep = (ln & 2) ? v2[1] : v2[0];
            float send = (ln & 2) ? v2[0] : v2[1];
            v1 = keep + __shfl_xor_sync(0xffffffffu, send, 2);
            v1 += __shfl_xor_sync(0xffffffffu, v1, 1);
        }
        if (!(ln & 1)) {
            int idx = ((ln >> 4) & 1) * 8 + ((ln >> 3) & 1) * 4 +
                      ((ln >> 2) & 1) * 2 + ((ln >> 1) & 1);
            s_S[(HH * LL + idx) * SST + m] = v1;
        }
    }

    // wait for prefetched C, then GEMM
    asm volatile("cp.async.wait_group 0;" ::: "memory");
    __syncthreads();

    // ======== GEMM: OUT[64,128] = S^T[64,136] @ C[136,128] + b2 ========
    // k-split: warps 0-7 k in [0,68), warps 8-15 k in [68,136).
    // warp (w&7) owns m = (w&7)*8..+7 ; lane te owns e = te*4..+3
    const int te = ln;
    const int w8 = (warp & 7) * 8;
    const bool gA = warp < 8;
    const int kbeg = gA ? 0 : 68;
    unsigned long long acc[4][4];
    if (gA) {
        const float4 bvv = *(const float4*)&s_b2[te * 4];
#pragma unroll
        for (int mp = 0; mp < 4; mp++) {
            acc[mp][0] = pk2(bvv.x, bvv.x);
            acc[mp][1] = pk2(bvv.y, bvv.y);
            acc[mp][2] = pk2(bvv.z, bvv.z);
            acc[mp][3] = pk2(bvv.w, bvv.w);
        }
    } else {
#pragma unroll
        for (int mp = 0; mp < 4; mp++)
#pragma unroll
            for (int i = 0; i < 4; i++) acc[mp][i] = pk2(0.f, 0.f);
    }
#pragma unroll 4
    for (int k = kbeg; k < kbeg + 68; k++) {
        const float4 c4 = *(const float4*)&s_C[k * EE + te * 4];
        const float4 sA = *(const float4*)&s_S[k * SST + w8];
        const float4 sB = *(const float4*)&s_S[k * SST + w8 + 4];
        unsigned long long cc0 = pk2(c4.x, c4.x), cc1 = pk2(c4.y, c4.y);
        unsigned long long cc2 = pk2(c4.z, c4.z), cc3 = pk2(c4.w, c4.w);
        unsigned long long sp[4] = {pk2(sA.x, sA.y), pk2(sA.z, sA.w),
                                    pk2(sB.x, sB.y), pk2(sB.z, sB.w)};
#pragma unroll
        for (int mp = 0; mp < 4; mp++) {
            fma2(acc[mp][0], sp[mp], cc0);
            fma2(acc[mp][1], sp[mp], cc1);
            fma2(acc[mp][2], sp[mp], cc2);
            fma2(acc[mp][3], sp[mp], cc3);
        }
    }
    __syncthreads();  // all s_C reads done; s_C reusable as reduction scratch
    float* s_red = s_C;  // [m*EE + e], 8192 floats
    if (!gA) {
#pragma unroll
        for (int mp = 0; mp < 4; mp++) {
            float lo0, hi0, lo1, hi1, lo2, hi2, lo3, hi3;
            upk2(acc[mp][0], lo0, hi0);
            upk2(acc[mp][1], lo1, hi1);
            upk2(acc[mp][2], lo2, hi2);
            upk2(acc[mp][3], lo3, hi3);
            int m0 = w8 + mp * 2;
            *(float4*)&s_red[m0 * EE + te * 4] = make_float4(lo0, lo1, lo2, lo3);
            *(float4*)&s_red[(m0 + 1) * EE + te * 4] = make_float4(hi0, hi1, hi2, hi3);
        }
    }
    __syncthreads();
    if (gA) {
        float* outb = out + (size_t)bn * MM * EE;
#pragma unroll
        for (int mp = 0; mp < 4; mp++) {
            float lo0, hi0, lo1, hi1, lo2, hi2, lo3, hi3;
            upk2(acc[mp][0], lo0, hi0);
            upk2(acc[mp][1], lo1, hi1);
            upk2(acc[mp][2], lo2, hi2);
            upk2(acc[mp][3], lo3, hi3);
            int m0 = w8 + mp * 2;
            const float4 ra = *(const float4*)&s_red[m0 * EE + te * 4];
            const float4 rb = *(const float4*)&s_red[(m0 + 1) * EE + te * 4];
            *(float4*)&outb[(size_t)m0 * EE + te * 4] =
                make_float4(lo0 + ra.x, lo1 + ra.y, lo2 + ra.z, lo3 + ra.w);
            *(float4*)&outb[(size_t)(m0 + 1) * EE + te * 4] =
                make_float4(hi0 + rb.x, hi1 + rb.y, hi2 + rb.z, hi3 + rb.w);
        }
    }
}

// =========================== launch ======================================
extern "C" void kernel_launch(void* const* d_in, const int* in_sizes, int n_in,
                              void* d_out, int out_size) {
    const float* agent = (const float*)d_in[0];
    const float* lanes = (const float*)d_in[1];
    const float* We = (const float*)d_in[2];
    const float* be = (const float*)d_in[3];
    const float* Wa = (const float*)d_in[4];
    const float* ba = (const float*)d_in[5];
    const float* pe = (const float*)d_in[6];
    const float* Wq = (const float*)d_in[7];
    const float* bq = (const float*)d_in[8];
    const float* Wk = (const float*)d_in[9];
    const float* bk = (const float*)d_in[10];
    const float* Wv = (const float*)d_in[11];
    const float* bv = (const float*)d_in[12];
    const float* Wo = (const float*)d_in[13];
    const float* bo = (const float*)d_in[14];
    const float* Wp = (const float*)d_in[15];
    const float* bp = (const float*)d_in[16];
    float* outp = (float*)d_out;

    const int smem_bytes = SM_TOTAL_FLOATS * sizeof(float);  // ~123.2 KB
    cudaFuncSetAttribute(fused_kernel, cudaFuncAttributeMaxDynamicSharedMemorySize,
                         smem_bytes);

    fused_kernel<<<NBLK, NTHR, smem_bytes>>>(agent, lanes, We, be, Wa, ba, pe,
                                             Wq, bq, Wk, bk, Wv, bv, Wo, bo, Wp, bp,
                                             outp);
}